// round 16
// baseline (speedup 1.0000x reference)
#include <cuda_runtime.h>
#include <math.h>
#include <stdint.h>

#define HH 128
#define WW 128
#define CC 64
#define BB 8
#define HW (HH*WW)

// scratch (device globals — no allocations allowed)
__device__ float  g_off[BB*18*HW];      // offset channels
__device__ float  g_mask[BB*9*HW];      // sigmoid(mask)
__device__ float2 g_wd[9*8*4*64];       // DCN B frags (k,kb,tg,oc) = (w[c][oc], w[c+4][oc])
__device__ float2 g_wo[9*8*4*32];       // OFF B frags (27 oc padded to 32)
__device__ float  g_sum[2*BB*CC];       // sums / sumsqs
__device__ float4 g_xq[BB*16*HW];       // x repacked: quad q=(g,r): (c0,c0+4,c0+8,c0+12), c0=16g+r

// ---------------------------------------------------------------------------
__device__ __forceinline__ uint32_t tf32u(float f){
    uint32_t u; asm("cvt.rna.tf32.f32 %0, %1;" : "=r"(u) : "f"(f)); return u;
}
__device__ __forceinline__ float tf32f(float f){ return __uint_as_float(tf32u(f)); }

__device__ __forceinline__ void mma8(float* d, const uint32_t* a, const uint32_t* b){
    asm volatile("mma.sync.aligned.m16n8k8.row.col.f32.tf32.tf32.f32 "
        "{%0,%1,%2,%3}, {%4,%5,%6,%7}, {%8,%9}, {%0,%1,%2,%3};"
        : "+f"(d[0]), "+f"(d[1]), "+f"(d[2]), "+f"(d[3])
        : "r"(a[0]), "r"(a[1]), "r"(a[2]), "r"(a[3]), "r"(b[0]), "r"(b[1]));
}

// ---------------------------------------------------------------------------
// Kernel W: pack B fragments (tf32-rounded) + zero stats accumulators
// ---------------------------------------------------------------------------
__global__ void k_wt(const float* __restrict__ wd, const float* __restrict__ wo){
    int idx = blockIdx.x*256 + threadIdx.x;
    if (idx < 2*BB*CC) g_sum[idx] = 0.f;
    if (idx < 9*8*4*64){
        int oc = idx & 63, r = idx >> 6;
        int tg = r & 3;  r >>= 2;
        int kb = r & 7;  int k = r >> 3;
        int c0 = kb*8 + tg;
        g_wd[idx] = make_float2(tf32f(wd[(oc*64 + c0)*9 + k]),
                                tf32f(wd[(oc*64 + c0+4)*9 + k]));
    }
    if (idx < 9*8*4*32){
        int oc = idx & 31, r = idx >> 5;
        int tg = r & 3;  r >>= 2;
        int kb = r & 7;  int k = r >> 3;
        int c0 = kb*8 + tg;
        float v0 = (oc < 27) ? wo[(oc*64 + c0)*9 + k]   : 0.f;
        float v1 = (oc < 27) ? wo[(oc*64 + c0+4)*9 + k] : 0.f;
        g_wo[idx] = make_float2(tf32f(v0), tf32f(v1));
    }
}

// ---------------------------------------------------------------------------
// Kernel X: repack x into channel-quads. quad q: g=q>>2, r=q&3, c0=16g+r;
// g_xq[(b*16+q)*HW + p] = (x[c0], x[c0+4], x[c0+8], x[c0+12]) at pixel p.
// Coalesced reads (4 streams) + coalesced float4 writes.
// ---------------------------------------------------------------------------
__global__ void __launch_bounds__(256)
k_xt(const float* __restrict__ x){
    int q = blockIdx.x, b = blockIdx.y;
    int g = q >> 2, r = q & 3, c0 = g*16 + r;
    const float* p0 = x + ((size_t)(b*CC + c0))*HW;
    float4* dst = g_xq + ((size_t)(b*16 + q))*HW;
    for (int j = threadIdx.x; j < HW; j += 256)
        dst[j] = make_float4(p0[j], p0[4*HW + j], p0[8*HW + j], p0[12*HW + j]);
}

// ---------------------------------------------------------------------------
// Kernel 1: offset conv 64->27 + bias + sigmoid(mask). block = (row, batch).
// Channel-chunked: 2 chunks of 16 planes -> smem 53.8KB -> 4 CTAs/SM.
// Staging reads quad float4s: 8 LDG.128 per (thread, chunk).
// ---------------------------------------------------------------------------
#define OFF_PS 420                       // float2 stride per plane
#define OFF_SMEM (16*OFF_PS*8)           // 53760 bytes

__global__ void __launch_bounds__(256, 4)
k_off_t(const float* __restrict__ x, const float* __restrict__ bOff){
    extern __shared__ __align__(16) float sm[];
    float2* s_v2 = (float2*)sm;

    int t = threadIdx.x, lane = t & 31, wid = t >> 5;
    int i = blockIdx.x, b = blockIdx.y;
    int tg = lane & 3, gq = lane >> 2;
    int px0 = (wid & 3) * 32, n0 = (wid >> 2) * 16;

    float acc[2][2][4];
    #pragma unroll
    for (int mt = 0; mt < 2; mt++)
        #pragma unroll
        for (int nt = 0; nt < 2; nt++)
            #pragma unroll
            for (int q = 0; q < 4; q++) acc[mt][nt][q] = 0.f;

    #pragma unroll 1
    for (int cc = 0; cc < 2; cc++){
        if (cc) __syncthreads();
        // stage 3 rows x 32c (16 pair-planes) from quads [8cc, 8cc+8)
        #pragma unroll
        for (int sub = 0; sub < 2; sub++){
            int j = sub*256 + t;
            if (j < 408){
                int r = (j >= 272) ? 2 : ((j >= 136) ? 1 : 0);
                int col = j - r*136;
                int gi = i - 1 + r, gj = col - 1;
                bool ok = ((unsigned)gi < HH) && ((unsigned)gj < WW);
                int ad = min(max(gi,0),HH-1)*WW + min(max(gj,0),WW-1);
                const float4* base = g_xq + ((size_t)(b*16 + cc*8))*HW + ad;
                float2* dst = s_v2 + j;
                #pragma unroll
                for (int qi = 0; qi < 8; qi++){
                    const int gl = qi >> 2, rr = qi & 3;
                    const int plA = 8*gl + rr;           // local planes
                    float4 v = ok ? base[qi*HW] : make_float4(0.f,0.f,0.f,0.f);
                    dst[ plA   *OFF_PS] = make_float2(tf32f(v.x), tf32f(v.y));
                    dst[(plA+4)*OFF_PS] = make_float2(tf32f(v.z), tf32f(v.w));
                }
            }
        }
        __syncthreads();

        #pragma unroll 1
        for (int k = 0; k < 9; k++){
            int base = (k/3)*136 + (k%3);
            const float2* wb = g_wo + k*1024;
            #pragma unroll
            for (int kb4 = 0; kb4 < 4; kb4++){
                const float2* vp = s_v2 + (kb4*4 + tg)*OFF_PS + base;
                uint32_t afr[2][4];
                #pragma unroll
                for (int mt = 0; mt < 2; mt++){
                    int pxb = px0 + mt*16 + gq;
                    float2 f01 = vp[pxb], f23 = vp[pxb + 8];
                    afr[mt][0] = __float_as_uint(f01.x);
                    afr[mt][1] = __float_as_uint(f23.x);
                    afr[mt][2] = __float_as_uint(f01.y);
                    afr[mt][3] = __float_as_uint(f23.y);
                }
                #pragma unroll
                for (int nt = 0; nt < 2; nt++){
                    float2 bw = wb[((cc*4 + kb4)*4 + tg)*32 + n0 + nt*8 + gq];
                    uint32_t bfr[2] = { __float_as_uint(bw.x), __float_as_uint(bw.y) };
                    mma8(acc[0][nt], afr[0], bfr);
                    mma8(acc[1][nt], afr[1], bfr);
                }
            }
        }
    }
    __syncthreads();

    float* s_out = sm;   // [32][132]
    #pragma unroll
    for (int mt = 0; mt < 2; mt++)
        #pragma unroll
        for (int nt = 0; nt < 2; nt++){
            int cA = n0 + nt*8 + 2*tg, rA = px0 + mt*16 + gq;
            s_out[ cA   *132 + rA    ] = acc[mt][nt][0];
            s_out[(cA+1)*132 + rA    ] = acc[mt][nt][1];
            s_out[ cA   *132 + rA + 8] = acc[mt][nt][2];
            s_out[(cA+1)*132 + rA + 8] = acc[mt][nt][3];
        }
    __syncthreads();

    #pragma unroll
    for (int r = 0; r < 14; r++){
        int idx = r*256 + t;
        if (idx < 27*128){
            int o = idx >> 7, px = idx & 127;
            float v = s_out[o*132 + px] + bOff[o];
            if (o < 18)
                g_off[((size_t)(b*18 + o))*HW + i*WW + px] = v;
            else
                g_mask[((size_t)(b*9 + o-18))*HW + i*WW + px] = 1.f/(1.f + __expf(-v));
        }
    }
}

// ---------------------------------------------------------------------------
// Kernel 2: deformable conv. block = (row i, batch b), M = 128 px.
// Gather from g_xq quads: 32 LDG.128 per thread-tap (was 128 LDG.32);
// 4 base pointers + compile-time immediate offsets.
// B single SMEM buffer staged during gather. 2 syncs/tap.
// smem 51.2KB, launch_bounds(256,4) -> 4 CTAs/SM.
// ---------------------------------------------------------------------------
#define DVS 132                          // float2 stride per s_v plane
#define DSB 4224                         // float2 index of B buffer
#define DCN_SMEM ((4224+2176)*8)         // 51200 bytes

__global__ void __launch_bounds__(256, 4)
k_dcn_t(const float* __restrict__ x, float* __restrict__ out){
    extern __shared__ __align__(16) float sm[];
    float2* s_v2 = (float2*)sm;
    float2* bbuf = s_v2 + DSB;

    int t = threadIdx.x, lane = t & 31, wid = t >> 5;
    int i = blockIdx.x, b = blockIdx.y;
    int tg = lane & 3, gq = lane >> 2;
    int pxq = (wid & 3) * 32, n0 = (wid >> 2) * 32;
    int pp = t & 127, half = t >> 7;

    const float4* xh = g_xq + ((size_t)(b*16 + half*8))*HW;  // quads [8h,8h+8)
    float2* sv0 = s_v2 + half*16*DVS + pp;                    // local plane base

    float acc[2][4][4];
    #pragma unroll
    for (int mt = 0; mt < 2; mt++)
        #pragma unroll
        for (int nt = 0; nt < 4; nt++)
            #pragma unroll
            for (int q = 0; q < 4; q++) acc[mt][nt][q] = 0.f;

    float w0, w1, w2, w3;
    int   a0, a1, a2, a3;

    // bilinear params for tap kk, pixel pp -> registers
    #define PARAMS(kk) do {                                                   \
        int k_ = (kk);                                                        \
        int ky_ = k_/3 - 1, kx_ = k_%3 - 1;                                   \
        size_t ofb_ = ((size_t)(b*18 + 2*k_))*HW + (size_t)i*WW + pp;         \
        float oy_ = g_off[ofb_], ox_ = g_off[ofb_ + HW];                      \
        float m_  = g_mask[((size_t)(b*9 + k_))*HW + i*WW + pp];              \
        float ys_ = (float)(i + ky_) + oy_;                                   \
        float xs_ = (float)(pp + kx_) + ox_;                                  \
        float y0f_ = floorf(ys_), x0f_ = floorf(xs_);                         \
        float wy1_ = ys_ - y0f_, wy0_ = 1.f - wy1_;                           \
        float wx1_ = xs_ - x0f_, wx0_ = 1.f - wx1_;                           \
        int r0_ = (int)y0f_, c0_ = (int)x0f_;                                 \
        bool vr0_ = (unsigned)r0_     < HH, vr1_ = (unsigned)(r0_+1) < HH;    \
        bool vc0_ = (unsigned)c0_     < WW, vc1_ = (unsigned)(c0_+1) < WW;    \
        int rc0_ = min(max(r0_,  0), HH-1)*WW, rc1_ = min(max(r0_+1,0), HH-1)*WW; \
        int cc0_ = min(max(c0_,  0), WW-1),    cc1_ = min(max(c0_+1,0), WW-1);    \
        w0 = (vr0_ && vc0_) ? wy0_*wx0_*m_ : 0.f;  a0 = rc0_ + cc0_;          \
        w1 = (vr0_ && vc1_) ? wy0_*wx1_*m_ : 0.f;  a1 = rc0_ + cc1_;          \
        w2 = (vr1_ && vc0_) ? wy1_*wx0_*m_ : 0.f;  a2 = rc1_ + cc0_;          \
        w3 = (vr1_ && vc1_) ? wy1_*wx1_*m_ : 0.f;  a3 = rc1_ + cc1_;          \
    } while(0)

    PARAMS(0);

    #pragma unroll 1
    for (int k = 0; k < 9; k++){
        // ---- phase 1: gather(k) + Bstage(k) ----
        {
            const float4* P0 = xh + a0;
            const float4* P1 = xh + a1;
            const float4* P2 = xh + a2;
            const float4* P3 = xh + a3;
            #pragma unroll
            for (int qi = 0; qi < 8; qi++){
                const int gl = qi >> 2, rr = qi & 3;
                const int plA = 8*gl + rr;             // compile-time local plane
                float4 F0 = P0[qi*HW], F1 = P1[qi*HW], F2 = P2[qi*HW], F3 = P3[qi*HW];
                float vx = w0*F0.x + w1*F1.x + w2*F2.x + w3*F3.x;
                float vy = w0*F0.y + w1*F1.y + w2*F2.y + w3*F3.y;
                float vz = w0*F0.z + w1*F1.z + w2*F2.z + w3*F3.z;
                float vw = w0*F0.w + w1*F1.w + w2*F2.w + w3*F3.w;
                sv0[ plA   *DVS] = make_float2(tf32f(vx), tf32f(vy));
                sv0[(plA+4)*DVS] = make_float2(tf32f(vz), tf32f(vw));
            }
        }
        {   // stage B tap k (single buffer; read only after the sync below)
            const float2* src = g_wd + (size_t)k*2048;
            #pragma unroll
            for (int r = 0; r < 8; r++){
                int j = r*256 + t;
                bbuf[(j >> 6)*68 + (j & 63)] = src[j];
            }
        }
        __syncthreads();

        // ---- phase 2: params(k+1) + MMA(k) ----
        if (k < 8) PARAMS(k+1);

        #pragma unroll
        for (int kb = 0; kb < 8; kb++){
            const float2* vp = s_v2 + (kb*4 + tg)*DVS;
            uint32_t afr[2][4];
            #pragma unroll
            for (int mt = 0; mt < 2; mt++){
                int pxb = pxq + mt*16 + gq;
                float2 f01 = vp[pxb], f23 = vp[pxb + 8];
                afr[mt][0] = __float_as_uint(f01.x);
                afr[mt][1] = __float_as_uint(f23.x);
                afr[mt][2] = __float_as_uint(f01.y);
                afr[mt][3] = __float_as_uint(f23.y);
            }
            const float2* bp = bbuf + (kb*4 + tg)*68 + n0;
            #pragma unroll
            for (int nt = 0; nt < 4; nt++){
                float2 bw = bp[nt*8 + gq];
                uint32_t bfr[2] = { __float_as_uint(bw.x), __float_as_uint(bw.y) };
                mma8(acc[0][nt], afr[0], bfr);
                mma8(acc[1][nt], afr[1], bfr);
            }
        }
        __syncthreads();
    }

    // epilogue: stage [64oc][132] -> coalesced float4 stores + fused stats
    float* s_out = sm;
    #pragma unroll
    for (int mt = 0; mt < 2; mt++)
        #pragma unroll
        for (int nt = 0; nt < 4; nt++){
            int cA = n0 + nt*8 + 2*tg, rA = pxq + mt*16 + gq;
            s_out[ cA   *132 + rA    ] = acc[mt][nt][0];
            s_out[(cA+1)*132 + rA    ] = acc[mt][nt][1];
            s_out[ cA   *132 + rA + 8] = acc[mt][nt][2];
            s_out[(cA+1)*132 + rA + 8] = acc[mt][nt][3];
        }
    __syncthreads();

    #pragma unroll
    for (int r = 0; r < 8; r++){
        int oc = r*8 + wid;
        float4 v = *(float4*)&s_out[oc*132 + lane*4];
        *(float4*)&out[((size_t)(b*CC + oc))*HW + i*WW + lane*4] = v;
        float s  = (v.x + v.y) + (v.z + v.w);
        float ss = fmaf(v.x, v.x, fmaf(v.y, v.y, fmaf(v.z, v.z, v.w*v.w)));
        #pragma unroll
        for (int d = 16; d > 0; d >>= 1){
            s  += __shfl_xor_sync(0xFFFFFFFFu, s,  d);
            ss += __shfl_xor_sync(0xFFFFFFFFu, ss, d);
        }
        if (lane == 0){
            atomicAdd(&g_sum[b*CC + oc], s);
            atomicAdd(&g_sum[BB*CC + b*CC + oc], ss);
        }
    }
}

// ---------------------------------------------------------------------------
// Kernel 3: normalize + relu in place (stats fused into k_dcn_t)
// ---------------------------------------------------------------------------
__global__ void k_norm(float* __restrict__ y){
    int bc = blockIdx.x;
    int t = threadIdx.x;
    float mean = g_sum[bc] * (1.f/16384.f);
    float var  = g_sum[BB*CC + bc] * (1.f/16384.f) - mean*mean;
    float rstd = rsqrtf(var + 1e-5f);
    float4* p = (float4*)(y + (size_t)bc * HW);
    #pragma unroll
    for (int r = 0; r < 16; r++){
        float4 v = p[r*256 + t];
        v.x = fmaxf((v.x - mean)*rstd, 0.f);
        v.y = fmaxf((v.y - mean)*rstd, 0.f);
        v.z = fmaxf((v.z - mean)*rstd, 0.f);
        v.w = fmaxf((v.w - mean)*rstd, 0.f);
        p[r*256 + t] = v;
    }
}

// ---------------------------------------------------------------------------
extern "C" void kernel_launch(void* const* d_in, const int* in_sizes, int n_in,
                              void* d_out, int out_size){
    const float* x     = (const float*)d_in[0];
    const float* w_off = (const float*)d_in[1];
    const float* b_off = (const float*)d_in[2];
    const float* w_dcn = (const float*)d_in[3];
    // d_in[4] = b_dcn: cancelled by instance norm.
    float* out = (float*)d_out;

    cudaFuncSetAttribute(k_off_t, cudaFuncAttributeMaxDynamicSharedMemorySize, OFF_SMEM);
    cudaFuncSetAttribute(k_dcn_t, cudaFuncAttributeMaxDynamicSharedMemorySize, DCN_SMEM);

    k_wt<<<144, 256>>>(w_dcn, w_off);
    k_xt<<<dim3(16, BB), 256>>>(x);        // launch #2
    k_off_t<<<dim3(HH, BB), 256, OFF_SMEM>>>(x, b_off);   // #3
    k_dcn_t<<<dim3(HH, BB), 256, DCN_SMEM>>>(x, out);     // #4 (ncu slot)
    k_norm<<<BB*CC, 256>>>(out);
}

// round 17
// speedup vs baseline: 1.1154x; 1.1154x over previous
#include <cuda_runtime.h>
#include <cuda_fp16.h>
#include <math.h>
#include <stdint.h>

#define HH 128
#define WW 128
#define CC 64
#define BB 8
#define HW (HH*WW)

// scratch (device globals — no allocations allowed)
__device__ float  g_off[BB*18*HW];      // offset channels
__device__ float  g_mask[BB*9*HW];      // sigmoid(mask)
__device__ float2 g_wd[9*8*4*64];       // DCN B frags (k,kb,tg,oc) = (w[c][oc], w[c+4][oc])
__device__ float2 g_wo[9*8*4*32];       // OFF B frags (27 oc padded to 32)
__device__ float  g_sum[2*BB*CC];       // sums / sumsqs
__device__ uint4  g_xh[BB*8*HW];        // x as fp16: (b,u,p) -> half2 pairs (8u+s, 8u+s+4), s=0..3

// ---------------------------------------------------------------------------
__device__ __forceinline__ uint32_t tf32u(float f){
    uint32_t u; asm("cvt.rna.tf32.f32 %0, %1;" : "=r"(u) : "f"(f)); return u;
}
__device__ __forceinline__ float tf32f(float f){ return __uint_as_float(tf32u(f)); }

__device__ __forceinline__ void mma8(float* d, const uint32_t* a, const uint32_t* b){
    asm volatile("mma.sync.aligned.m16n8k8.row.col.f32.tf32.tf32.f32 "
        "{%0,%1,%2,%3}, {%4,%5,%6,%7}, {%8,%9}, {%0,%1,%2,%3};"
        : "+f"(d[0]), "+f"(d[1]), "+f"(d[2]), "+f"(d[3])
        : "r"(a[0]), "r"(a[1]), "r"(a[2]), "r"(a[3]), "r"(b[0]), "r"(b[1]));
}

// ---------------------------------------------------------------------------
// Kernel W: pack B fragments (tf32-rounded) + zero stats accumulators
// ---------------------------------------------------------------------------
__global__ void k_wt(const float* __restrict__ wd, const float* __restrict__ wo){
    int idx = blockIdx.x*256 + threadIdx.x;
    if (idx < 2*BB*CC) g_sum[idx] = 0.f;
    if (idx < 9*8*4*64){
        int oc = idx & 63, r = idx >> 6;
        int tg = r & 3;  r >>= 2;
        int kb = r & 7;  int k = r >> 3;
        int c0 = kb*8 + tg;
        g_wd[idx] = make_float2(tf32f(wd[(oc*64 + c0)*9 + k]),
                                tf32f(wd[(oc*64 + c0+4)*9 + k]));
    }
    if (idx < 9*8*4*32){
        int oc = idx & 31, r = idx >> 5;
        int tg = r & 3;  r >>= 2;
        int kb = r & 7;  int k = r >> 3;
        int c0 = kb*8 + tg;
        float v0 = (oc < 27) ? wo[(oc*64 + c0)*9 + k]   : 0.f;
        float v1 = (oc < 27) ? wo[(oc*64 + c0+4)*9 + k] : 0.f;
        g_wo[idx] = make_float2(tf32f(v0), tf32f(v1));
    }
}

// ---------------------------------------------------------------------------
// Kernel X: pack x -> fp16 octets. (b,u,p): halves = x[8u+s], x[8u+s+4] pairs.
// ---------------------------------------------------------------------------
__global__ void __launch_bounds__(256)
k_xh(const float* __restrict__ x){
    int u = blockIdx.x, b = blockIdx.y;
    const float* p0 = x + ((size_t)(b*CC + u*8))*HW;
    uint4* dst = g_xh + ((size_t)(b*8 + u))*HW;
    for (int j = threadIdx.x; j < HW; j += 256){
        __half2 h[4];
        #pragma unroll
        for (int s = 0; s < 4; s++)
            h[s] = __floats2half2_rn(p0[s*HW + j], p0[(s+4)*HW + j]);
        uint4 v;
        v.x = *(uint32_t*)&h[0]; v.y = *(uint32_t*)&h[1];
        v.z = *(uint32_t*)&h[2]; v.w = *(uint32_t*)&h[3];
        dst[j] = v;
    }
}

// ---------------------------------------------------------------------------
// Kernel 1: offset conv 64->27 + bias + sigmoid(mask). block = (row, batch).
// Channel-chunked: 2 chunks of 16 planes -> smem 53.8KB -> 4 CTAs/SM.
// Staging from fp32 x, hoisted decomposition + immediate offsets (R13 ver).
// ---------------------------------------------------------------------------
#define OFF_PS 420                       // float2 stride per plane
#define OFF_SMEM (16*OFF_PS*8)           // 53760 bytes

__global__ void __launch_bounds__(256, 4)
k_off_t(const float* __restrict__ x, const float* __restrict__ bOff){
    extern __shared__ __align__(16) float sm[];
    float2* s_v2 = (float2*)sm;

    int t = threadIdx.x, lane = t & 31, wid = t >> 5;
    int i = blockIdx.x, b = blockIdx.y;
    int tg = lane & 3, gq = lane >> 2;
    int px0 = (wid & 3) * 32, n0 = (wid >> 2) * 16;

    float acc[2][2][4];
    #pragma unroll
    for (int mt = 0; mt < 2; mt++)
        #pragma unroll
        for (int nt = 0; nt < 2; nt++)
            #pragma unroll
            for (int q = 0; q < 4; q++) acc[mt][nt][q] = 0.f;

    #pragma unroll 1
    for (int cc = 0; cc < 2; cc++){
        if (cc) __syncthreads();
        #pragma unroll
        for (int sub = 0; sub < 2; sub++){
            int j = sub*256 + t;
            if (j < 408){
                int r = (j >= 272) ? 2 : ((j >= 136) ? 1 : 0);
                int col = j - r*136;
                int gi = i - 1 + r, gj = col - 1;
                bool ok = ((unsigned)gi < HH) && ((unsigned)gj < WW);
                int ad = min(max(gi,0),HH-1)*WW + min(max(gj,0),WW-1);
                const float* base = x + ((size_t)(b*CC + cc*32))*HW + ad;
                float2* dst = s_v2 + j;
                #pragma unroll
                for (int pl = 0; pl < 16; pl++){
                    const int c = ((pl >> 2) << 3) + (pl & 3);
                    float v0 = ok ? base[c*HW]     : 0.f;
                    float v1 = ok ? base[(c+4)*HW] : 0.f;
                    dst[pl*OFF_PS] = make_float2(tf32f(v0), tf32f(v1));
                }
            }
        }
        __syncthreads();

        #pragma unroll 1
        for (int k = 0; k < 9; k++){
            int base = (k/3)*136 + (k%3);
            const float2* wb = g_wo + k*1024;
            #pragma unroll
            for (int kb4 = 0; kb4 < 4; kb4++){
                const float2* vp = s_v2 + (kb4*4 + tg)*OFF_PS + base;
                uint32_t afr[2][4];
                #pragma unroll
                for (int mt = 0; mt < 2; mt++){
                    int pxb = px0 + mt*16 + gq;
                    float2 f01 = vp[pxb], f23 = vp[pxb + 8];
                    afr[mt][0] = __float_as_uint(f01.x);
                    afr[mt][1] = __float_as_uint(f23.x);
                    afr[mt][2] = __float_as_uint(f01.y);
                    afr[mt][3] = __float_as_uint(f23.y);
                }
                #pragma unroll
                for (int nt = 0; nt < 2; nt++){
                    float2 bw = wb[((cc*4 + kb4)*4 + tg)*32 + n0 + nt*8 + gq];
                    uint32_t bfr[2] = { __float_as_uint(bw.x), __float_as_uint(bw.y) };
                    mma8(acc[0][nt], afr[0], bfr);
                    mma8(acc[1][nt], afr[1], bfr);
                }
            }
        }
    }
    __syncthreads();

    float* s_out = sm;   // [32][132]
    #pragma unroll
    for (int mt = 0; mt < 2; mt++)
        #pragma unroll
        for (int nt = 0; nt < 2; nt++){
            int cA = n0 + nt*8 + 2*tg, rA = px0 + mt*16 + gq;
            s_out[ cA   *132 + rA    ] = acc[mt][nt][0];
            s_out[(cA+1)*132 + rA    ] = acc[mt][nt][1];
            s_out[ cA   *132 + rA + 8] = acc[mt][nt][2];
            s_out[(cA+1)*132 + rA + 8] = acc[mt][nt][3];
        }
    __syncthreads();

    #pragma unroll
    for (int r = 0; r < 14; r++){
        int idx = r*256 + t;
        if (idx < 27*128){
            int o = idx >> 7, px = idx & 127;
            float v = s_out[o*132 + px] + bOff[o];
            if (o < 18)
                g_off[((size_t)(b*18 + o))*HW + i*WW + px] = v;
            else
                g_mask[((size_t)(b*9 + o-18))*HW + i*WW + px] = 1.f/(1.f + __expf(-v));
        }
    }
}

// ---------------------------------------------------------------------------
// Kernel 2: deformable conv. block = (row i, batch b), M = 128 px.
// Gather from g_xh (fp16): 16 LDG.128 per thread-tap, 8 channels each —
// HALF the L1 bytes of the fp32 gather. Weighted in fp32, tf32-rounded.
// B single SMEM buffer staged during gather. 2 syncs/tap.
// smem 51.2KB, launch_bounds(256,4) -> 4 CTAs/SM.
// ---------------------------------------------------------------------------
#define DVS 132                          // float2 stride per s_v plane
#define DSB 4224                         // float2 index of B buffer
#define DCN_SMEM ((4224+2176)*8)         // 51200 bytes

__global__ void __launch_bounds__(256, 4)
k_dcn_t(const float* __restrict__ x, float* __restrict__ out){
    extern __shared__ __align__(16) float sm[];
    float2* s_v2 = (float2*)sm;
    float2* bbuf = s_v2 + DSB;

    int t = threadIdx.x, lane = t & 31, wid = t >> 5;
    int i = blockIdx.x, b = blockIdx.y;
    int tg = lane & 3, gq = lane >> 2;
    int pxq = (wid & 3) * 32, n0 = (wid >> 2) * 32;
    int pp = t & 127, half = t >> 7;

    const uint4* xh = g_xh + ((size_t)(b*8 + half*4))*HW;   // u in [4h, 4h+4)
    float2* sv0 = s_v2 + half*16*DVS + pp;                   // planes [16h, 16h+16)

    float acc[2][4][4];
    #pragma unroll
    for (int mt = 0; mt < 2; mt++)
        #pragma unroll
        for (int nt = 0; nt < 4; nt++)
            #pragma unroll
            for (int q = 0; q < 4; q++) acc[mt][nt][q] = 0.f;

    float w0, w1, w2, w3;
    int   a0, a1, a2, a3;

    #define PARAMS(kk) do {                                                   \
        int k_ = (kk);                                                        \
        int ky_ = k_/3 - 1, kx_ = k_%3 - 1;                                   \
        size_t ofb_ = ((size_t)(b*18 + 2*k_))*HW + (size_t)i*WW + pp;         \
        float oy_ = g_off[ofb_], ox_ = g_off[ofb_ + HW];                      \
        float m_  = g_mask[((size_t)(b*9 + k_))*HW + i*WW + pp];              \
        float ys_ = (float)(i + ky_) + oy_;                                   \
        float xs_ = (float)(pp + kx_) + ox_;                                  \
        float y0f_ = floorf(ys_), x0f_ = floorf(xs_);                         \
        float wy1_ = ys_ - y0f_, wy0_ = 1.f - wy1_;                           \
        float wx1_ = xs_ - x0f_, wx0_ = 1.f - wx1_;                           \
        int r0_ = (int)y0f_, c0_ = (int)x0f_;                                 \
        bool vr0_ = (unsigned)r0_     < HH, vr1_ = (unsigned)(r0_+1) < HH;    \
        bool vc0_ = (unsigned)c0_     < WW, vc1_ = (unsigned)(c0_+1) < WW;    \
        int rc0_ = min(max(r0_,  0), HH-1)*WW, rc1_ = min(max(r0_+1,0), HH-1)*WW; \
        int cc0_ = min(max(c0_,  0), WW-1),    cc1_ = min(max(c0_+1,0), WW-1);    \
        w0 = (vr0_ && vc0_) ? wy0_*wx0_*m_ : 0.f;  a0 = rc0_ + cc0_;          \
        w1 = (vr0_ && vc1_) ? wy0_*wx1_*m_ : 0.f;  a1 = rc0_ + cc1_;          \
        w2 = (vr1_ && vc0_) ? wy1_*wx0_*m_ : 0.f;  a2 = rc1_ + cc0_;          \
        w3 = (vr1_ && vc1_) ? wy1_*wx1_*m_ : 0.f;  a3 = rc1_ + cc1_;          \
    } while(0)

    PARAMS(0);

    #pragma unroll 1
    for (int k = 0; k < 9; k++){
        // ---- phase 1: gather(k) + Bstage(k) ----
        {
            const uint4* P0 = xh + a0;
            const uint4* P1 = xh + a1;
            const uint4* P2 = xh + a2;
            const uint4* P3 = xh + a3;
            #pragma unroll
            for (int uu = 0; uu < 4; uu++){
                uint4 F0 = P0[uu*HW], F1 = P1[uu*HW], F2 = P2[uu*HW], F3 = P3[uu*HW];
                const uint32_t* q0 = &F0.x; const uint32_t* q1 = &F1.x;
                const uint32_t* q2 = &F2.x; const uint32_t* q3 = &F3.x;
                #pragma unroll
                for (int s = 0; s < 4; s++){
                    float2 f0 = __half22float2(*(const __half2*)&q0[s]);
                    float2 f1 = __half22float2(*(const __half2*)&q1[s]);
                    float2 f2 = __half22float2(*(const __half2*)&q2[s]);
                    float2 f3 = __half22float2(*(const __half2*)&q3[s]);
                    float vx = w0*f0.x + w1*f1.x + w2*f2.x + w3*f3.x;
                    float vy = w0*f0.y + w1*f1.y + w2*f2.y + w3*f3.y;
                    sv0[(uu*4 + s)*DVS] = make_float2(tf32f(vx), tf32f(vy));
                }
            }
        }
        {   // stage B tap k (single buffer; read only after the sync below)
            const float2* src = g_wd + (size_t)k*2048;
            #pragma unroll
            for (int r = 0; r < 8; r++){
                int j = r*256 + t;
                bbuf[(j >> 6)*68 + (j & 63)] = src[j];
            }
        }
        __syncthreads();

        // ---- phase 2: params(k+1) + MMA(k) ----
        if (k < 8) PARAMS(k+1);

        #pragma unroll
        for (int kb = 0; kb < 8; kb++){
            const float2* vp = s_v2 + (kb*4 + tg)*DVS;
            uint32_t afr[2][4];
            #pragma unroll
            for (int mt = 0; mt < 2; mt++){
                int pxb = pxq + mt*16 + gq;
                float2 f01 = vp[pxb], f23 = vp[pxb + 8];
                afr[mt][0] = __float_as_uint(f01.x);
                afr[mt][1] = __float_as_uint(f23.x);
                afr[mt][2] = __float_as_uint(f01.y);
                afr[mt][3] = __float_as_uint(f23.y);
            }
            const float2* bp = bbuf + (kb*4 + tg)*68 + n0;
            #pragma unroll
            for (int nt = 0; nt < 4; nt++){
                float2 bw = bp[nt*8 + gq];
                uint32_t bfr[2] = { __float_as_uint(bw.x), __float_as_uint(bw.y) };
                mma8(acc[0][nt], afr[0], bfr);
                mma8(acc[1][nt], afr[1], bfr);
            }
        }
        __syncthreads();
    }

    // epilogue: stage [64oc][132] -> coalesced float4 stores + fused stats
    float* s_out = sm;
    #pragma unroll
    for (int mt = 0; mt < 2; mt++)
        #pragma unroll
        for (int nt = 0; nt < 4; nt++){
            int cA = n0 + nt*8 + 2*tg, rA = pxq + mt*16 + gq;
            s_out[ cA   *132 + rA    ] = acc[mt][nt][0];
            s_out[(cA+1)*132 + rA    ] = acc[mt][nt][1];
            s_out[ cA   *132 + rA + 8] = acc[mt][nt][2];
            s_out[(cA+1)*132 + rA + 8] = acc[mt][nt][3];
        }
    __syncthreads();

    #pragma unroll
    for (int r = 0; r < 8; r++){
        int oc = r*8 + wid;
        float4 v = *(float4*)&s_out[oc*132 + lane*4];
        *(float4*)&out[((size_t)(b*CC + oc))*HW + i*WW + lane*4] = v;
        float s  = (v.x + v.y) + (v.z + v.w);
        float ss = fmaf(v.x, v.x, fmaf(v.y, v.y, fmaf(v.z, v.z, v.w*v.w)));
        #pragma unroll
        for (int d = 16; d > 0; d >>= 1){
            s  += __shfl_xor_sync(0xFFFFFFFFu, s,  d);
            ss += __shfl_xor_sync(0xFFFFFFFFu, ss, d);
        }
        if (lane == 0){
            atomicAdd(&g_sum[b*CC + oc], s);
            atomicAdd(&g_sum[BB*CC + b*CC + oc], ss);
        }
    }
}

// ---------------------------------------------------------------------------
// Kernel 3: normalize + relu in place (stats fused into k_dcn_t)
// ---------------------------------------------------------------------------
__global__ void k_norm(float* __restrict__ y){
    int bc = blockIdx.x;
    int t = threadIdx.x;
    float mean = g_sum[bc] * (1.f/16384.f);
    float var  = g_sum[BB*CC + bc] * (1.f/16384.f) - mean*mean;
    float rstd = rsqrtf(var + 1e-5f);
    float4* p = (float4*)(y + (size_t)bc * HW);
    #pragma unroll
    for (int r = 0; r < 16; r++){
        float4 v = p[r*256 + t];
        v.x = fmaxf((v.x - mean)*rstd, 0.f);
        v.y = fmaxf((v.y - mean)*rstd, 0.f);
        v.z = fmaxf((v.z - mean)*rstd, 0.f);
        v.w = fmaxf((v.w - mean)*rstd, 0.f);
        p[r*256 + t] = v;
    }
}

// ---------------------------------------------------------------------------
extern "C" void kernel_launch(void* const* d_in, const int* in_sizes, int n_in,
                              void* d_out, int out_size){
    const float* x     = (const float*)d_in[0];
    const float* w_off = (const float*)d_in[1];
    const float* b_off = (const float*)d_in[2];
    const float* w_dcn = (const float*)d_in[3];
    // d_in[4] = b_dcn: cancelled by instance norm.
    float* out = (float*)d_out;

    cudaFuncSetAttribute(k_off_t, cudaFuncAttributeMaxDynamicSharedMemorySize, OFF_SMEM);
    cudaFuncSetAttribute(k_dcn_t, cudaFuncAttributeMaxDynamicSharedMemorySize, DCN_SMEM);

    k_wt<<<144, 256>>>(w_dcn, w_off);
    k_xh<<<dim3(8, BB), 256>>>(x);                         // #2
    k_off_t<<<dim3(HH, BB), 256, OFF_SMEM>>>(x, b_off);    // #3
    k_dcn_t<<<dim3(HH, BB), 256, DCN_SMEM>>>(x, out);      // #4 (ncu slot)
    k_norm<<<BB*CC, 256>>>(out);
}